// round 17
// baseline (speedup 1.0000x reference)
#include <cuda_runtime.h>
#include <cuda_fp16.h>
#include <cuda_bf16.h>
#include <cstdint>

#define N_TOKENS 32
#define IN_F     4096
#define OUT_F    11008
#define KC       64
#define NCHUNK   (IN_F / KC)       // 64
#define THREADS  128               // fallback kernel
#define FTHREADS 256               // fast kernel: 8 warps

// ---- fast-path (int32 W, fp32 x) config: TILE_M = 32 ----
#define FTILE_M  32
#define FA_BYTES (FTILE_M * 128)   // 4096
#define FX_BYTES (N_TOKENS * 128)  // 4096 per tile
#define F_SMEM   (2 * FA_BYTES + 4 * FX_BYTES + 1024)   // 25600

// ---- generic fallback config: TILE_M = 64 ----
#define TILE_M   64
#define A_BYTES  (TILE_M * 128)
#define B_BYTES  (N_TOKENS * 128)
#define OFF_A0   0
#define OFF_B0   (A_BYTES)
#define OFF_A1   (A_BYTES + B_BYTES)
#define OFF_B1   (OFF_A1 + A_BYTES)
#define SMEM_BYTES (2 * (A_BYTES + B_BYTES) + 1024)

// runtime dtype flags
__device__ int g_qint32;   // 1: qweight int32, 0: int8
__device__ int g_xdt;      // 0: fp32, 1: fp16, 2: bf16

// pre-converted, pre-swizzled X tiles: [NCHUNK][4KB tile image]
__device__ __align__(16) unsigned char g_xtiles[NCHUNK * 4096];

// ---------------- helpers ----------------
__device__ __forceinline__ uint32_t smem_u32(const void* p) {
    uint32_t a;
    asm("{ .reg .u64 t; cvta.to.shared.u64 t, %1; cvt.u32.u64 %0, t; }" : "=r"(a) : "l"(p));
    return a;
}
__device__ __forceinline__ uint32_t swz(uint32_t off) {   // SW128: Swizzle<3,4,3>
    return off ^ ((off >> 3) & 0x70);
}
__device__ __forceinline__ void ldsm_x4(uint32_t& r0, uint32_t& r1, uint32_t& r2,
                                        uint32_t& r3, uint32_t addr) {
    asm volatile("ldmatrix.sync.aligned.m8n8.x4.shared.b16 {%0,%1,%2,%3}, [%4];"
                 : "=r"(r0), "=r"(r1), "=r"(r2), "=r"(r3) : "r"(addr));
}
__device__ __forceinline__ void mma16816(float* c, uint32_t a0, uint32_t a1,
                                         uint32_t a2, uint32_t a3,
                                         uint32_t b0, uint32_t b1) {
    asm volatile(
        "mma.sync.aligned.m16n8k16.row.col.f32.f16.f16.f32 "
        "{%0,%1,%2,%3}, {%4,%5,%6,%7}, {%8,%9}, {%0,%1,%2,%3};"
        : "+f"(c[0]), "+f"(c[1]), "+f"(c[2]), "+f"(c[3])
        : "r"(a0), "r"(a1), "r"(a2), "r"(a3), "r"(b0), "r"(b1));
}
__device__ __forceinline__ void cp_async16(uint32_t smem_dst, const void* gsrc) {
    asm volatile("cp.async.cg.shared.global [%0], [%1], 16;"
                 :: "r"(smem_dst), "l"(gsrc) : "memory");
}

// ---------------- dtype detection (parallel, deterministic decision) ----------------
__global__ void detect_kernel(const void* x, const void* qw) {
    __shared__ float s_m[3];
    const int tid = threadIdx.x;   // 128 threads
    if (tid < 3) s_m[tid] = 0.f;

    const int* qi = (const int*)qw;
    int ok = 1;
    if (tid < 64) {
        int v = qi[tid];
        ok = (v >= -128 && v <= 127);
    }
    __syncthreads();

    uint32_t w = ((const uint32_t*)x)[tid];
    float a = fabsf(__uint_as_float(w));
    if (!isfinite(a) || a > 16.f) a = 16.f;
    if (a < 1e-6f) a = 1e-6f;
    float mh = 0.f, mb = 0.f;
#pragma unroll
    for (int hsel = 0; hsel < 2; ++hsel) {
        uint32_t hbits = (w >> (16 * hsel)) & 0xFFFFu;
        float ah = fabsf(__half2float(__ushort_as_half((unsigned short)hbits)));
        if (!isfinite(ah) || ah > 16.f) ah = 16.f;
        if (ah < 1e-6f) ah = 1e-6f;
        mh += 0.5f * ah;
        float ab = fabsf(__uint_as_float(hbits << 16));
        if (!isfinite(ab) || ab > 16.f) ab = 16.f;
        if (ab < 1e-6f) ab = 1e-6f;
        mb += 0.5f * ab;
    }
    atomicAdd(&s_m[0], a);
    atomicAdd(&s_m[1], mh);
    atomicAdd(&s_m[2], mb);

    int allok = __syncthreads_and(ok);

    if (tid == 0) {
        g_qint32 = allok ? 1 : 0;
        int best = 0;
        float bd = 1e30f;
#pragma unroll
        for (int k = 0; k < 3; ++k) {
            float d = fabsf(logf((s_m[k] * (1.0f / 128.0f)) / 0.798f));
            if (d < bd) { bd = d; best = k; }
        }
        g_xdt = best;
    }
}

// ---------------- xprep: fp32 X -> fp16, pre-swizzled per-chunk tile images ----------------
__global__ void xprep_kernel(const float* __restrict__ x) {
    if (!(g_qint32 == 1 && g_xdt == 0)) return;
    const int c   = blockIdx.x;
    const int tid = threadIdx.x;
    const int tok = tid >> 2;
    const int q   = tid & 3;

    const float* xp = x + (size_t)tok * IN_F + c * KC + q * 16;
    uint4 f[4];
#pragma unroll
    for (int j = 0; j < 4; ++j) f[j] = ((const uint4*)xp)[j];

    uint32_t h[8];
#pragma unroll
    for (int j = 0; j < 4; ++j) {
        __half2 p0 = __floats2half2_rn(__uint_as_float(f[j].x), __uint_as_float(f[j].y));
        __half2 p1 = __floats2half2_rn(__uint_as_float(f[j].z), __uint_as_float(f[j].w));
        h[2 * j]     = *(uint32_t*)&p0;
        h[2 * j + 1] = *(uint32_t*)&p1;
    }
    unsigned char* base = g_xtiles + (size_t)c * 4096 + tok * 128;
    const uint32_t xorm = (uint32_t)((tok & 7) << 4);
    *(uint4*)(base + (((uint32_t)(q * 32))      ^ xorm)) = make_uint4(h[0], h[1], h[2], h[3]);
    *(uint4*)(base + (((uint32_t)(q * 32 + 16)) ^ xorm)) = make_uint4(h[4], h[5], h[6], h[7]);
}

// ================= FAST PATH: 256 threads, intra-chunk K-split across warp halves =================
__global__ void __launch_bounds__(FTHREADS, 2)
qlin_fast_kernel(const float* __restrict__ x,
                 const int* __restrict__ qw,
                 const float* __restrict__ scales,
                 const float* __restrict__ bias,
                 float* __restrict__ out)
{
    if (!(g_qint32 == 1 && g_xdt == 0)) return;

    extern __shared__ char smem_raw[];
    const uint32_t sb = (smem_u32(smem_raw) + 1023u) & ~1023u;
    const uint32_t abuf[2] = {sb, sb + 4096};
    const uint32_t xbuf[4] = {sb + 8192, sb + 12288, sb + 16384, sb + 20480};

    const int tid  = threadIdx.x;
    const int wid  = tid >> 5;
    const int lane = tid & 31;
    const int wk   = wid >> 2;     // k-half: 0 -> ks 0,1 ; 1 -> ks 2,3
    const int wq   = wid & 3;      // (m-half, token-half) quadrant
    const int row0 = blockIdx.x * FTILE_M;

    // ---- W staging: 256 threads, row = tid>>3 (0..31), seg = tid&7 ----
    // LDG0 covers row bytes [seg*16, ...), LDG1 at +128B. 4 lines per LDG warp-wide.
    const int lrow = tid >> 3;
    const int seg  = tid & 7;
    const int* wbase = qw + (size_t)(row0 + lrow) * IN_F + seg * 4;
    const uint32_t a_sts0 = swz((uint32_t)(lrow * 128 + seg * 8));
    const uint32_t a_sts1 = swz((uint32_t)(lrow * 128 + 64 + seg * 8));

    // W prefetch depth 4: 2 uint4 per stage
    uint4 wr[4][2];
#pragma unroll
    for (int s = 0; s < 4; ++s) {
        wr[s][0] = *(const uint4*)(wbase + s * KC);
        wr[s][1] = *(const uint4*)(wbase + s * KC + 32);
    }

    // pre-issue X tiles 0,1,2 (16B per thread per tile)
    const unsigned char* xsrc = g_xtiles;
#pragma unroll
    for (int p = 0; p < 3; ++p) {
        cp_async16(xbuf[p] + tid * 16, xsrc + (size_t)p * 4096 + tid * 16);
        asm volatile("cp.async.commit_group;" ::: "memory");
    }

    float acc[2][4];
#pragma unroll
    for (int i = 0; i < 2; ++i)
#pragma unroll
        for (int j = 0; j < 4; ++j) acc[i][j] = 0.0f;

    // ldmatrix per-lane addressing (quadrant wq as in R14; k offset by wk)
    const int am = lane >> 3;
    const uint32_t a_noswz = (uint32_t)(((wq & 1) * 16 + (am & 1) * 8 + (lane & 7)) * 128 +
                                        (am >> 1) * 16);
    const uint32_t b_noswz = (uint32_t)(((wq >> 1) * 16 + (am >> 1) * 8 + (lane & 7)) * 128 +
                                        (am & 1) * 16);
    const uint32_t kbase = (uint32_t)(wk * 64);   // byte offset of this warp's k-half

#pragma unroll 1
    for (int cc = 0; cc < NCHUNK; cc += 4) {
#pragma unroll
        for (int u = 0; u < 4; ++u) {
            const int c = cc + u;

            // ---- convert W stage u -> STS A buf (u&1) ----
#pragma unroll
            for (int j = 0; j < 2; ++j) {
                uint32_t t1, t2, pk;
                asm("prmt.b32 %0, %1, %2, 0x0040;" : "=r"(t1) : "r"(wr[u][j].x), "r"(wr[u][j].y));
                asm("prmt.b32 %0, %1, %2, 0x0040;" : "=r"(t2) : "r"(wr[u][j].z), "r"(wr[u][j].w));
                asm("prmt.b32 %0, %1, %2, 0x5410;" : "=r"(pk) : "r"(t1), "r"(t2));
                uint32_t uu = pk ^ 0x80808080u;
                uint32_t lo, hh, h0, h1;
                asm("prmt.b32 %0, %1, %2, 0x5140;" : "=r"(lo) : "r"(uu), "r"(0x64646464u));
                asm("prmt.b32 %0, %1, %2, 0x7362;" : "=r"(hh) : "r"(uu), "r"(0x64646464u));
                asm("sub.rn.f16x2 %0, %1, %2;" : "=r"(h0) : "r"(lo), "r"(0x64806480u));
                asm("sub.rn.f16x2 %0, %1, %2;" : "=r"(h1) : "r"(hh), "r"(0x64806480u));
                asm volatile("st.shared.v2.b32 [%0], {%1, %2};"
                             :: "r"(abuf[u & 1] + (j ? a_sts1 : a_sts0)),
                                "r"(h0), "r"(h1) : "memory");
            }

            // X tile c complete (<=2 newer groups pending)
            asm volatile("cp.async.wait_group 2;" ::: "memory");
            __syncthreads();

            // issue X tile c+3 into ring slot (u+3)&3
            if (c + 3 < NCHUNK) {
                cp_async16(xbuf[(u + 3) & 3] + tid * 16,
                           xsrc + (size_t)(c + 3) * 4096 + tid * 16);
            }
            asm volatile("cp.async.commit_group;" ::: "memory");

            // prefetch W chunk c+4 into stage u
            if (c + 4 < NCHUNK) {
                const int k4 = (c + 4) * KC;
                wr[u][0] = *(const uint4*)(wbase + k4);
                wr[u][1] = *(const uint4*)(wbase + k4 + 32);
            }

            // ---- compute this warp's 2 k-steps of chunk c ----
            const uint32_t ab = abuf[u & 1], bbx = xbuf[u];
#pragma unroll
            for (int j = 0; j < 2; ++j) {
                const uint32_t kbyte = kbase + (uint32_t)(j * 32);
                uint32_t a0, a1, a2, a3;
                ldsm_x4(a0, a1, a2, a3, ab + swz(a_noswz + kbyte));
                uint32_t b0, b1, b2, b3;
                ldsm_x4(b0, b1, b2, b3, bbx + swz(b_noswz + kbyte));
                mma16816(acc[0], a0, a1, a2, a3, b0, b1);
                mma16816(acc[1], a0, a1, a2, a3, b2, b3);
            }
        }
    }

    // ---- cross-warp K reduce: wk=1 accs into wk=0 via SMEM (4KB in abuf area) ----
    __syncthreads();   // all ldsm reads of smem done
    if (wk == 1) {
        const uint32_t dst = sb + (uint32_t)((wid - 4) * 32 + lane) * 32;
        asm volatile("st.shared.v4.b32 [%0], {%1,%2,%3,%4};"
                     :: "r"(dst),
                        "r"(__float_as_uint(acc[0][0])), "r"(__float_as_uint(acc[0][1])),
                        "r"(__float_as_uint(acc[0][2])), "r"(__float_as_uint(acc[0][3]))
                     : "memory");
        asm volatile("st.shared.v4.b32 [%0], {%1,%2,%3,%4};"
                     :: "r"(dst + 16),
                        "r"(__float_as_uint(acc[1][0])), "r"(__float_as_uint(acc[1][1])),
                        "r"(__float_as_uint(acc[1][2])), "r"(__float_as_uint(acc[1][3]))
                     : "memory");
    }
    __syncthreads();
    if (wk == 0) {
        const uint32_t src = sb + (uint32_t)tid * 32;
        uint32_t p0, p1, p2, p3, q0, q1, q2, q3;
        asm volatile("ld.shared.v4.b32 {%0,%1,%2,%3}, [%4];"
                     : "=r"(p0), "=r"(p1), "=r"(p2), "=r"(p3) : "r"(src));
        asm volatile("ld.shared.v4.b32 {%0,%1,%2,%3}, [%4];"
                     : "=r"(q0), "=r"(q1), "=r"(q2), "=r"(q3) : "r"(src + 16));
        acc[0][0] += __uint_as_float(p0); acc[0][1] += __uint_as_float(p1);
        acc[0][2] += __uint_as_float(p2); acc[0][3] += __uint_as_float(p3);
        acc[1][0] += __uint_as_float(q0); acc[1][1] += __uint_as_float(q1);
        acc[1][2] += __uint_as_float(q2); acc[1][3] += __uint_as_float(q3);

        // ---- epilogue ----
        const int g = lane >> 2, tig = lane & 3;
        const int o0 = row0 + (wq & 1) * 16 + g;
        const int o1 = o0 + 8;
        const int ntbase = (wq >> 1) * 16;
        const float s0 = scales[o0], bi0 = bias[o0];
        const float s1 = scales[o1], bi1 = bias[o1];

#pragma unroll
        for (int nt = 0; nt < 2; ++nt) {
            const int t0 = ntbase + nt * 8 + tig * 2;
            out[(size_t)t0       * OUT_F + o0] = acc[nt][0] * s0 + bi0;
            out[(size_t)(t0 + 1) * OUT_F + o0] = acc[nt][1] * s0 + bi0;
            out[(size_t)t0       * OUT_F + o1] = acc[nt][2] * s1 + bi1;
            out[(size_t)(t0 + 1) * OUT_F + o1] = acc[nt][3] * s1 + bi1;
        }
    }
}

// ================= GENERIC FALLBACK (previously passing kernel, unchanged) =================
__global__ void __launch_bounds__(THREADS, 2)
qlin_mma_kernel(const void* __restrict__ xv,
                const void* __restrict__ qwv,
                const void* __restrict__ scalesv,
                const void* __restrict__ biasv,
                void* __restrict__ outv)
{
    if (g_qint32 == 1 && g_xdt == 0) return;   // fast path handles this combo

    extern __shared__ char smem_raw[];
    const uint32_t sb = (smem_u32(smem_raw) + 1023u) & ~1023u;
    const uint32_t aoff[2] = {sb + OFF_A0, sb + OFF_A1};
    const uint32_t boff[2] = {sb + OFF_B0, sb + OFF_B1};

    const int q32 = g_qint32;
    const int xdt = g_xdt;

    const int tid  = threadIdx.x;
    const int wid  = tid >> 5;
    const int lane = tid & 31;
    const int row0 = blockIdx.x * TILE_M;

    const int r = tid >> 1, h = tid & 1;
    const int tok = tid >> 2, seg = tid & 3;

    const int8_t* w8base  = (const int8_t*)qwv + (size_t)(row0 + r) * IN_F + h * 32;
    const int*    w32base = (const int*)qwv    + (size_t)(row0 + r) * IN_F + h * 32;
    const __half* x16base = (const __half*)xv  + (size_t)tok * IN_F + seg * 16;
    const float*  x32base = (const float*)xv   + (size_t)tok * IN_F + seg * 16;

    uint4 wraw[2][8];
    uint4 xraw[2][4];

    auto load_w = [&](int s, int c) {
        if (q32) {
            const uint4* p = (const uint4*)(w32base + c * KC);
#pragma unroll
            for (int j = 0; j < 8; ++j) wraw[s][j] = p[j];
        } else {
            const uint4* p = (const uint4*)(w8base + c * KC);
            wraw[s][0] = p[0];
            wraw[s][1] = p[1];
        }
    };
    auto load_x = [&](int s, int c) {
        if (xdt == 0) {
            const uint4* p = (const uint4*)(x32base + (size_t)c * KC);
#pragma unroll
            for (int j = 0; j < 4; ++j) xraw[s][j] = p[j];
        } else {
            const uint4* p = (const uint4*)(x16base + (size_t)c * KC);
            xraw[s][0] = p[0];
            xraw[s][1] = p[1];
        }
    };

    load_w(0, 0); load_x(0, 0);
    load_w(1, 1); load_x(1, 1);

    float acc[4][4];
#pragma unroll
    for (int i = 0; i < 4; ++i)
#pragma unroll
        for (int j = 0; j < 4; ++j) acc[i][j] = 0.0f;

    const int am = lane >> 3;
    const uint32_t a_noswz =
        (uint32_t)((wid * 16 + (am & 1) * 8 + (lane & 7)) * 128 + (am >> 1) * 16);
    const uint32_t b_row_local =
        (uint32_t)(((am >> 1) * 8 + (lane & 7)) * 128 + (am & 1) * 16);

    const uint32_t a_sts_base = (uint32_t)(r * 128 + h * 64);
    const uint32_t b_sts_base = (uint32_t)(tok * 128 + seg * 32);

#pragma unroll 1
    for (int c = 0; c < NCHUNK; ++c) {
        const int s = c & 1;

        const uint32_t* wrp = (const uint32_t*)wraw[s];
        uint32_t pk[8];
        if (q32) {
#pragma unroll
            for (int i = 0; i < 8; ++i) {
                uint32_t t1, t2;
                asm("prmt.b32 %0, %1, %2, 0x0040;" : "=r"(t1) : "r"(wrp[4 * i]),     "r"(wrp[4 * i + 1]));
                asm("prmt.b32 %0, %1, %2, 0x0040;" : "=r"(t2) : "r"(wrp[4 * i + 2]), "r"(wrp[4 * i + 3]));
                asm("prmt.b32 %0, %1, %2, 0x5410;" : "=r"(pk[i]) : "r"(t1), "r"(t2));
            }
        } else {
#pragma unroll
            for (int i = 0; i < 8; ++i) pk[i] = wrp[i];
        }
        uint32_t o2[16];
#pragma unroll
        for (int i = 0; i < 8; ++i) {
            uint32_t u = pk[i] ^ 0x80808080u;
            uint32_t lo, hi2;
            asm("prmt.b32 %0, %1, %2, 0x5140;" : "=r"(lo)  : "r"(u), "r"(0x64646464u));
            asm("prmt.b32 %0, %1, %2, 0x7362;" : "=r"(hi2) : "r"(u), "r"(0x64646464u));
            asm("sub.rn.f16x2 %0, %1, %2;" : "=r"(o2[2 * i])     : "r"(lo),  "r"(0x64806480u));
            asm("sub.rn.f16x2 %0, %1, %2;" : "=r"(o2[2 * i + 1]) : "r"(hi2), "r"(0x64806480u));
        }
#pragma unroll
        for (int q = 0; q < 4; ++q) {
            uint32_t addr = aoff[s] + swz(a_sts_base + q * 16);
            asm volatile("st.shared.v4.b32 [%0], {%1,%2,%3,%4};"
                         :: "r"(addr), "r"(o2[4 * q]), "r"(o2[4 * q + 1]),
                            "r"(o2[4 * q + 2]), "r"(o2[4 * q + 3]) : "memory");
        }

        uint32_t xb2[8];
        const uint32_t* xr = (const uint32_t*)xraw[s];
        if (xdt == 1) {
#pragma unroll
            for (int j = 0; j < 8; ++j) xb2[j] = xr[j];
        } else if (xdt == 0) {
#pragma unroll
            for (int j = 0; j < 8; ++j) {
                __half2 hp = __floats2half2_rn(__uint_as_float(xr[2 * j]),
                                               __uint_as_float(xr[2 * j + 1]));
                xb2[j] = *(uint32_t*)&hp;
            }
        } else {
#pragma unroll
            for (int j = 0; j < 8; ++j) {
                uint32_t w = xr[j];
                __half2 hp = __floats2half2_rn(__uint_as_float(w << 16),
                                               __uint_as_float(w & 0xFFFF0000u));
                xb2[j] = *(uint32_t*)&hp;
            }
        }
#pragma unroll
        for (int j = 0; j < 2; ++j) {
            uint32_t addr = boff[s] + swz(b_sts_base + j * 16);
            asm volatile("st.shared.v4.b32 [%0], {%1,%2,%3,%4};"
                         :: "r"(addr), "r"(xb2[4 * j]), "r"(xb2[4 * j + 1]),
                            "r"(xb2[4 * j + 2]), "r"(xb2[4 * j + 3]) : "memory");
        }

        __syncthreads();

        if (c + 2 < NCHUNK) { load_w(s, c + 2); load_x(s, c + 2); }

        const uint32_t ab = aoff[s], bb = boff[s];
#pragma unroll
        for (int ks = 0; ks < 4; ++ks) {
            const uint32_t kbyte = (uint32_t)(ks * 32);
            uint32_t a0, a1, a2, a3;
            ldsm_x4(a0, a1, a2, a3, ab + swz(a_noswz + kbyte));
            uint32_t b0, b1, b2, b3;
            ldsm_x4(b0, b1, b2, b3, bb + swz(b_row_local + kbyte));
            uint32_t b4, b5, b6, b7;
            ldsm_x4(b4, b5, b6, b7, bb + swz(b_row_local + 16 * 128 + kbyte));
            mma16816(acc[0], a0, a1, a2, a3, b0, b1);
            mma16816(acc[1], a0, a1, a2, a3, b2, b3);
            mma16816(acc[2], a0, a1, a2, a3, b4, b5);
            mma16816(acc[3], a0, a1, a2, a3, b6, b7);
        }
    }

    const int g = lane >> 2, tig = lane & 3;
    const int o0 = row0 + wid * 16 + g;
    const int o1 = o0 + 8;

    float s0, s1, bi0, bi1;
    if (xdt == 0) {
        s0  = ((const float*)scalesv)[o0]; s1  = ((const float*)scalesv)[o1];
        bi0 = ((const float*)biasv)[o0];   bi1 = ((const float*)biasv)[o1];
    } else if (xdt == 1) {
        s0  = __half2float(((const __half*)scalesv)[o0]);
        s1  = __half2float(((const __half*)scalesv)[o1]);
        bi0 = __half2float(((const __half*)biasv)[o0]);
        bi1 = __half2float(((const __half*)biasv)[o1]);
    } else {
        s0  = __uint_as_float(((uint32_t)((const unsigned short*)scalesv)[o0]) << 16);
        s1  = __uint_as_float(((uint32_t)((const unsigned short*)scalesv)[o1]) << 16);
        bi0 = __uint_as_float(((uint32_t)((const unsigned short*)biasv)[o0]) << 16);
        bi1 = __uint_as_float(((uint32_t)((const unsigned short*)biasv)[o1]) << 16);
    }

#pragma unroll
    for (int nt = 0; nt < 4; ++nt) {
        const int t0 = nt * 8 + tig * 2;
        float v00 = acc[nt][0] * s0 + bi0;
        float v01 = acc[nt][1] * s0 + bi0;
        float v10 = acc[nt][2] * s1 + bi1;
        float v11 = acc[nt][3] * s1 + bi1;
        size_t i00 = (size_t)t0 * OUT_F + o0, i01 = i00 + OUT_F;
        size_t i10 = (size_t)t0 * OUT_F + o1, i11 = i10 + OUT_F;
        if (xdt == 0) {
            float* o = (float*)outv;
            o[i00] = v00; o[i01] = v01; o[i10] = v10; o[i11] = v11;
        } else if (xdt == 1) {
            __half* o = (__half*)outv;
            o[i00] = __float2half(v00); o[i01] = __float2half(v01);
            o[i10] = __float2half(v10); o[i11] = __float2half(v11);
        } else {
            __nv_bfloat16* o = (__nv_bfloat16*)outv;
            o[i00] = __float2bfloat16(v00); o[i01] = __float2bfloat16(v01);
            o[i10] = __float2bfloat16(v10); o[i11] = __float2bfloat16(v11);
        }
    }
}

extern "C" void kernel_launch(void* const* d_in, const int* in_sizes, int n_in,
                              void* d_out, int out_size) {
    const void* x      = d_in[0];
    const void* qw     = d_in[1];
    const void* scales = d_in[2];
    const void* bias   = d_in[3];

    detect_kernel<<<1, 128>>>(x, qw);
    xprep_kernel<<<NCHUNK, 128>>>((const float*)x);

    dim3 fgrid(OUT_F / FTILE_M);   // 344 CTAs, 256 threads
    qlin_fast_kernel<<<fgrid, FTHREADS, F_SMEM>>>(
        (const float*)x, (const int*)qw, (const float*)scales,
        (const float*)bias, (float*)d_out);

    dim3 ggrid(OUT_F / TILE_M);    // 172 CTAs (early-exits when fast path ran)
    qlin_mma_kernel<<<ggrid, THREADS, SMEM_BYTES>>>(x, qw, scales, bias, d_out);
}